// round 10
// baseline (speedup 1.0000x reference)
#include <cuda_runtime.h>
#include <cuda_bf16.h>
#include <cstdint>
#include <math.h>

#define NSEQ 4096
#define BATCH 2
#define BN (BATCH*NSEQ)
#define FDIM 512
#define DDIM 64
#define MASKVAL (-12800.0f)
#define SCALE_LOG2E (0.125f*1.4426950408889634f)
#define SQ 72   // padded bf16 row stride for mma smem tiles

// ---------------- scratch (device globals; no allocation allowed) ----------------
__device__ float g_Q[(size_t)BN*DDIM];
__device__ float g_K[(size_t)BN*DDIM];
__device__ float g_C[(size_t)BATCH*NSEQ*NSEQ];       // C' = (QK^T/8)*log2e; above-diag of diag tiles = MASKVAL
__device__ unsigned short g_P[(size_t)BATCH*NSEQ*NSEQ]; // bf16 exp2(C'*fac) staging (67MB)
__device__ float g_ch[BN];                           // current charge
__device__ float g_chpt[4][BN];                      // transposed packed sqrt(ss)*charge history
__device__ float g_rs[BN];                           // rowsum accumulator
__device__ float g_recv[BN];                         // column sums (received)

__device__ __forceinline__ float sigmoidf_(float x){ return 1.f/(1.f+__expf(-x)); }
__device__ __forceinline__ float ex2_(float x){ float y; asm("ex2.approx.f32 %0, %1;" : "=f"(y) : "f"(x)); return y; }
__device__ __forceinline__ uint32_t smem_u32_(const void* p){
    uint32_t a;
    asm("{ .reg .u64 t; cvta.to.shared.u64 t, %1; cvt.u32.u64 %0, t; }" : "=r"(a) : "l"(p));
    return a;
}
__device__ __forceinline__ uint32_t packbf2_(float lo, float hi){
    uint32_t r; asm("cvt.rn.bf16x2.f32 %0, %1, %2;" : "=r"(r) : "f"(hi), "f"(lo)); return r;
}

// ---------------- Q/K projection + RoPE ----------------
__global__ void qk_rope_kernel(const float* __restrict__ feat,
                               const float* __restrict__ cosb,
                               const float* __restrict__ sinb,
                               const float* __restrict__ Wq,
                               const float* __restrict__ Wk)
{
    __shared__ float fs[16][64];
    __shared__ float qs[16][64];
    __shared__ float ks[16][64];
    int tid = threadIdx.x;
    int d = tid & 63, rg = tid >> 6;
    long rowbase = (long)blockIdx.x * 16;
    float accq[4] = {0,0,0,0}, acck[4] = {0,0,0,0};
    for (int f0 = 0; f0 < FDIM; f0 += 64){
        __syncthreads();
        for (int i = tid; i < 16*64; i += 256){
            int r = i >> 6, f = i & 63;
            fs[r][f] = feat[(rowbase + r)*FDIM + f0 + f];
        }
        __syncthreads();
        #pragma unroll 8
        for (int f = 0; f < 64; f++){
            float wq = Wq[(f0+f)*DDIM + d];
            float wk = Wk[(f0+f)*DDIM + d];
            #pragma unroll
            for (int i = 0; i < 4; i++){
                float fv = fs[rg*4+i][f];
                accq[i] = fmaf(fv, wq, accq[i]);
                acck[i] = fmaf(fv, wk, acck[i]);
            }
        }
    }
    __syncthreads();
    #pragma unroll
    for (int i = 0; i < 4; i++){ qs[rg*4+i][d] = accq[i]; ks[rg*4+i][d] = acck[i]; }
    __syncthreads();
    #pragma unroll
    for (int i = 0; i < 4; i++){
        int r = rg*4+i;
        long n = rowbase + r;
        int nn = (int)(n & (NSEQ-1));
        float c = cosb[nn*DDIM+d], s = sinb[nn*DDIM+d];
        float q = qs[r][d], k = ks[r][d];
        float qr = (d < 32) ? -qs[r][d+32] : qs[r][d-32];
        float kr = (d < 32) ? -ks[r][d+32] : ks[r][d-32];
        g_Q[n*DDIM+d] = q*c + qr*s;
        g_K[n*DDIM+d] = k*c + kr*s;
    }
}

// ---------------- initial charge + zero recv/rs/chpt ----------------
__global__ void charge0_kernel(const float* __restrict__ feat,
                               const float* __restrict__ cw,
                               const float* __restrict__ cb)
{
    int warp = threadIdx.x >> 5, lane = threadIdx.x & 31;
    long n = (long)blockIdx.x*8 + warp;
    if (n >= BN) return;
    float sum = 0.f;
    for (int f = lane; f < FDIM; f += 32) sum = fmaf(feat[n*FDIM+f], cw[f], sum);
    #pragma unroll
    for (int o = 16; o > 0; o >>= 1) sum += __shfl_down_sync(0xffffffffu, sum, o);
    if (lane == 0){
        g_ch[n] = sigmoidf_(sum + cb[0]);
        g_recv[n] = 0.f;
        g_rs[n] = 0.f;
        #pragma unroll
        for (int t = 0; t < 4; t++) g_chpt[t][n] = 0.f;
    }
}

// ---------------- gemm via mma.sync bf16 hi/lo: C' = QK^T*(log2e/8), masked ----------------
__global__ void __launch_bounds__(256) gemm_mma_kernel()
{
    extern __shared__ __nv_bfloat16 smb[];
    __nv_bfloat16* Qhi = smb;
    __nv_bfloat16* Qlo = smb + 128*SQ;
    __nv_bfloat16* Khi = smb + 2*128*SQ;
    __nv_bfloat16* Klo = smb + 3*128*SQ;

    int b = blockIdx.y;
    int kidx = blockIdx.x;
    int ti = (int)((sqrtf(8.f*(float)kidx + 1.f) - 1.f) * 0.5f);
    while ((ti+1)*(ti+2)/2 <= kidx) ti++;
    while (ti*(ti+1)/2 > kidx) ti--;
    int tj = kidx - ti*(ti+1)/2;

    const float* Qb = g_Q + ((long)b*NSEQ + (long)ti*128)*DDIM;
    const float* Kb = g_K + ((long)b*NSEQ + (long)tj*128)*DDIM;
    int tid = threadIdx.x;
    for (int i = tid; i < 128*32; i += 256){
        int r = i >> 5, c2 = i & 31;
        float2 q = *(const float2*)&Qb[r*64 + c2*2];
        float2 k = *(const float2*)&Kb[r*64 + c2*2];
        int o = r*SQ + c2*2;
        __nv_bfloat16 qhx = __float2bfloat16_rn(q.x), qhy = __float2bfloat16_rn(q.y);
        __nv_bfloat16 khx = __float2bfloat16_rn(k.x), khy = __float2bfloat16_rn(k.y);
        __nv_bfloat16 qlx = __float2bfloat16_rn(q.x - __bfloat162float(qhx));
        __nv_bfloat16 qly = __float2bfloat16_rn(q.y - __bfloat162float(qhy));
        __nv_bfloat16 klx = __float2bfloat16_rn(k.x - __bfloat162float(khx));
        __nv_bfloat16 kly = __float2bfloat16_rn(k.y - __bfloat162float(khy));
        *(__nv_bfloat162*)&Qhi[o] = __nv_bfloat162(qhx, qhy);
        *(__nv_bfloat162*)&Qlo[o] = __nv_bfloat162(qlx, qly);
        *(__nv_bfloat162*)&Khi[o] = __nv_bfloat162(khx, khy);
        *(__nv_bfloat162*)&Klo[o] = __nv_bfloat162(klx, kly);
    }
    __syncthreads();

    int lane = tid & 31, w = tid >> 5;
    int wm = (w & 1)*64, wn = (w >> 1)*32;

    float c[4][4][4] = {};

    uint32_t qhi_b = smem_u32_(Qhi), qlo_b = smem_u32_(Qlo);
    uint32_t khi_b = smem_u32_(Khi), klo_b = smem_u32_(Klo);

    int ar = lane & 15, ac8 = lane >> 4;
    int br = lane & 7,  bc8 = (lane >> 3) & 1;

    #pragma unroll
    for (int combo = 0; combo < 3; combo++){
        uint32_t abase = (combo == 2) ? qlo_b : qhi_b;
        uint32_t bbase = (combo == 1) ? klo_b : khi_b;
        #pragma unroll
        for (int k0 = 0; k0 < 64; k0 += 16){
            uint32_t a[4][4], bf[4][2];
            #pragma unroll
            for (int i = 0; i < 4; i++){
                uint32_t addr = abase + (uint32_t)(((wm + i*16 + ar)*SQ + k0 + ac8*8)*2);
                asm volatile("ldmatrix.sync.aligned.m8n8.x4.shared.b16 {%0,%1,%2,%3}, [%4];"
                    : "=r"(a[i][0]), "=r"(a[i][1]), "=r"(a[i][2]), "=r"(a[i][3]) : "r"(addr));
            }
            #pragma unroll
            for (int j = 0; j < 4; j++){
                uint32_t addr = bbase + (uint32_t)(((wn + j*8 + br)*SQ + k0 + bc8*8)*2);
                asm volatile("ldmatrix.sync.aligned.m8n8.x2.shared.b16 {%0,%1}, [%2];"
                    : "=r"(bf[j][0]), "=r"(bf[j][1]) : "r"(addr));
            }
            #pragma unroll
            for (int i = 0; i < 4; i++)
                #pragma unroll
                for (int j = 0; j < 4; j++)
                    asm volatile("mma.sync.aligned.m16n8k16.row.col.f32.bf16.bf16.f32 "
                        "{%0,%1,%2,%3}, {%4,%5,%6,%7}, {%8,%9}, {%0,%1,%2,%3};"
                        : "+f"(c[i][j][0]), "+f"(c[i][j][1]), "+f"(c[i][j][2]), "+f"(c[i][j][3])
                        : "r"(a[i][0]), "r"(a[i][1]), "r"(a[i][2]), "r"(a[i][3]),
                          "r"(bf[j][0]), "r"(bf[j][1]));
        }
    }

    // epilogue: scale, diag mask, direct stores (float2 per frag row)
    float* Cb = g_C + (size_t)b*NSEQ*NSEQ;
    bool diag = (ti == tj);
    int rq = lane >> 2, cq = (lane & 3)*2;
    #pragma unroll
    for (int i = 0; i < 4; i++){
        int lr0 = wm + i*16 + rq;
        #pragma unroll
        for (int j = 0; j < 4; j++){
            int lc = wn + j*8 + cq;
            float2 v0 = make_float2(c[i][j][0]*SCALE_LOG2E, c[i][j][1]*SCALE_LOG2E);
            float2 v1 = make_float2(c[i][j][2]*SCALE_LOG2E, c[i][j][3]*SCALE_LOG2E);
            if (diag){
                if (lr0 < lc)       v0.x = MASKVAL;
                if (lr0 < lc+1)     v0.y = MASKVAL;
                if (lr0+8 < lc)     v1.x = MASKVAL;
                if (lr0+8 < lc+1)   v1.y = MASKVAL;
            }
            size_t row0 = (size_t)(ti*128 + lr0);
            int col = tj*128 + lc;
            *(float2*)&Cb[row0*NSEQ + col] = v0;
            *(float2*)&Cb[(row0+8)*NSEQ + col] = v1;
        }
    }
}

// ---------------- exp-pass: e = exp2(C*f) -> P(bf16), row sums -> rs ----------------
template<int T>
__global__ void __launch_bounds__(256) exprow_kernel()
{
    int b  = blockIdx.z;
    int m0 = blockIdx.x * 512;
    int n0 = blockIdx.y * 64;
    if (m0 > n0 + 63) return;
    int lane = threadIdx.x & 31, wid = threadIdx.x >> 5;
    int nr0 = n0 + wid*8;
    const float* Cb = g_C + (size_t)b*NSEQ*NSEQ;
    unsigned short* Pb = g_P + (size_t)b*NSEQ*NSEQ;
    float acc[8] = {0.f,0.f,0.f,0.f,0.f,0.f,0.f,0.f};
    #pragma unroll
    for (int i = 0; i < 4; i++){
        int mchunk = m0 + i*128;
        if (mchunk > nr0 + 7) break;
        int m = mchunk + lane*4;
        float4 q[(T>0)?T:1];
        #pragma unroll
        for (int t = 0; t < T; t++) q[t] = *(const float4*)&g_chpt[t][b*NSEQ + m];
        #pragma unroll
        for (int r = 0; r < 8; r++){
            int n = nr0 + r;
            float4 cc = *(const float4*)&Cb[(size_t)n*NSEQ + m];
            float fx = 1.f, fy = 1.f, fz = 1.f, fw = 1.f;
            #pragma unroll
            for (int t = 0; t < T; t++){
                float cn = g_chpt[t][b*NSEQ + n];
                fx = fmaf(cn, q[t].x, fx);
                fy = fmaf(cn, q[t].y, fy);
                fz = fmaf(cn, q[t].z, fz);
                fw = fmaf(cn, q[t].w, fw);
            }
            float e0 = (T==0) ? ex2_(cc.x) : ex2_(cc.x*fx);
            float e1 = (T==0) ? ex2_(cc.y) : ex2_(cc.y*fy);
            float e2 = (T==0) ? ex2_(cc.z) : ex2_(cc.z*fz);
            float e3 = (T==0) ? ex2_(cc.w) : ex2_(cc.w*fw);
            uint2 pk = make_uint2(packbf2_(e0, e1), packbf2_(e2, e3));
            *(uint2*)&Pb[(size_t)n*NSEQ + m] = pk;
            acc[r] += (e0 + e1) + (e2 + e3);
        }
    }
    #pragma unroll
    for (int r = 0; r < 8; r++){
        float s = acc[r];
        #pragma unroll
        for (int o = 16; o > 0; o >>= 1) s += __shfl_down_sync(0xffffffffu, s, o);
        if (lane == 0 && s != 0.f) atomicAdd(&g_rs[b*NSEQ + nr0 + r], s);
    }
}

// ---------------- colsum over P: received += sum_n P[n][m]/rs[n] ----------------
__global__ void __launch_bounds__(256) colsumP_kernel()
{
    int b  = blockIdx.z;
    int m0 = blockIdx.x * 128;
    int n0 = blockIdx.y * 256;
    if (m0 > n0 + 255) return;
    int tid = threadIdx.x, lane = tid & 31, wid = tid >> 5;
    int m = m0 + lane*4;
    const unsigned short* Pb = g_P + (size_t)b*NSEQ*NSEQ;
    float4 acc = make_float4(0.f,0.f,0.f,0.f);
    int nbase = n0 + wid*32;
    #pragma unroll 4
    for (int k = 0; k < 32; k++){
        int n = nbase + k;
        if (m0 > n) continue;
        float irs = __frcp_rn(g_rs[b*NSEQ + n]);
        uint2 pv = *(const uint2*)&Pb[(size_t)n*NSEQ + m];
        float e0 = __uint_as_float(pv.x << 16);
        float e1 = __uint_as_float(pv.x & 0xFFFF0000u);
        float e2 = __uint_as_float(pv.y << 16);
        float e3 = __uint_as_float(pv.y & 0xFFFF0000u);
        acc.x = fmaf(e0, irs, acc.x);
        acc.y = fmaf(e1, irs, acc.y);
        acc.z = fmaf(e2, irs, acc.z);
        acc.w = fmaf(e3, irs, acc.w);
    }
    __shared__ float4 s4[256];
    s4[tid] = acc;
    __syncthreads();
    if (tid < 32){
        float4 t = s4[tid];
        #pragma unroll
        for (int r = 1; r < 8; r++){
            float4 o = s4[tid + r*32];
            t.x += o.x; t.y += o.y; t.z += o.z; t.w += o.w;
        }
        float* dst = &g_recv[b*NSEQ + m0 + tid*4];
        atomicAdd(dst+0, t.x);
        atomicAdd(dst+1, t.y);
        atomicAdd(dst+2, t.z);
        atomicAdd(dst+3, t.w);
    }
}

// ---------------- charge update + pack + re-zero recv/rs ----------------
__global__ void chargeupd_kernel(int t, const float* __restrict__ cdp,
                                        const float* __restrict__ ssp)
{
    int i = blockIdx.x*256 + threadIdx.x;
    if (i >= BN) return;
    float cd = *cdp, ss = *ssp;
    float r  = g_recv[i];
    float ch = g_ch[i] * (1.f - cd*sigmoidf_(r - 1.f));
    g_ch[i] = ch;
    g_chpt[t][i] = sqrtf(ss)*ch;
    g_recv[i] = 0.f;
    g_rs[i] = 0.f;
}

// ---------------- fused final: row-strip rowsum + normalized write ----------------
__global__ void __launch_bounds__(256) final_fused_kernel(float* __restrict__ out)
{
    __shared__ float P[NSEQ];
    __shared__ float red[9];
    int blk = blockIdx.x;
    int b = blk & 1;
    int n = (NSEQ-1) - (blk >> 1);           // long rows first
    const float* Crow = g_C + ((size_t)b*NSEQ + n)*NSEQ;
    int tid = threadIdx.x, lane = tid & 31, wid = tid >> 5;
    int L = ((n >> 7) + 1) << 7;             // row length rounded up to 128 (masked tail ~ 0)
    float cn0 = g_chpt[0][b*NSEQ+n];
    float cn1 = g_chpt[1][b*NSEQ+n];
    float cn2 = g_chpt[2][b*NSEQ+n];
    float cn3 = g_chpt[3][b*NSEQ+n];
    float sum = 0.f;
    for (int i = tid; i < (L >> 2); i += 256){
        float4 cc = ((const float4*)Crow)[i];
        int m = b*NSEQ + i*4;
        float4 t0 = *(const float4*)&g_chpt[0][m];
        float4 t1 = *(const float4*)&g_chpt[1][m];
        float4 t2 = *(const float4*)&g_chpt[2][m];
        float4 t3 = *(const float4*)&g_chpt[3][m];
        float fx = fmaf(cn0,t0.x, fmaf(cn1,t1.x, fmaf(cn2,t2.x, fmaf(cn3,t3.x, 1.f))));
        float fy = fmaf(cn0,t0.y, fmaf(cn1,t1.y, fmaf(cn2,t2.y, fmaf(cn3,t3.y, 1.f))));
        float fz = fmaf(cn0,t0.z, fmaf(cn1,t1.z, fmaf(cn2,t2.z, fmaf(cn3,t3.z, 1.f))));
        float fw = fmaf(cn0,t0.w, fmaf(cn1,t1.w, fmaf(cn2,t2.w, fmaf(cn3,t3.w, 1.f))));
        float p0 = ex2_(cc.x*fx), p1 = ex2_(cc.y*fy);
        float p2 = ex2_(cc.z*fz), p3 = ex2_(cc.w*fw);
        *(float4*)&P[i*4] = make_float4(p0,p1,p2,p3);
        sum += (p0 + p1) + (p2 + p3);
    }
    #pragma unroll
    for (int o = 16; o > 0; o >>= 1) sum += __shfl_down_sync(0xffffffffu, sum, o);
    if (lane == 0) red[wid] = sum;
    __syncthreads();
    if (tid == 0){
        float s = 0.f;
        #pragma unroll
        for (int w = 0; w < 8; w++) s += red[w];
        red[8] = 1.f / s;
    }
    __syncthreads();
    float irs = red[8];
    float* orow = out + ((size_t)b*NSEQ + n)*NSEQ;
    int L4 = L >> 2;
    for (int i = tid; i < NSEQ/4; i += 256){
        float4 v = make_float4(0.f,0.f,0.f,0.f);
        if (i < L4){
            float4 p = *(float4*)&P[i*4];
            v = make_float4(p.x*irs, p.y*irs, p.z*irs, p.w*irs);
        }
        *(float4*)&orow[i*4] = v;
    }
}

// ---------------- launch ----------------
extern "C" void kernel_launch(void* const* d_in, const int* in_sizes, int n_in,
                              void* d_out, int out_size)
{
    const float* feat = (const float*)d_in[0];
    const float* cosb = (const float*)d_in[1];
    const float* sinb = (const float*)d_in[2];
    // d_in[3] = mask (causal; not needed)
    const float* Wq   = (const float*)d_in[4];
    const float* Wk   = (const float*)d_in[5];
    const float* cw   = (const float*)d_in[6];
    const float* cb   = (const float*)d_in[7];
    const float* ssp  = (const float*)d_in[8];
    const float* cdp  = (const float*)d_in[9];
    float* out = (float*)d_out;

    const int GSMEM = 4*128*SQ*2;   // 73728 bytes
    static int smem_set = 0;
    if (!smem_set){
        cudaFuncSetAttribute(gemm_mma_kernel, cudaFuncAttributeMaxDynamicSharedMemorySize, GSMEM);
        smem_set = 1;
    }

    qk_rope_kernel<<<BN/16, 256>>>(feat, cosb, sinb, Wq, Wk);
    charge0_kernel<<<BN/8, 256>>>(feat, cw, cb);

    const int T = NSEQ/128;
    dim3 g3(T*(T+1)/2, BATCH);
    gemm_mma_kernel<<<g3, 256, GSMEM>>>();

    dim3 grow(NSEQ/512, NSEQ/64, BATCH);
    dim3 gcol(NSEQ/128, NSEQ/256, BATCH);

    exprow_kernel<0><<<grow, 256>>>();
    colsumP_kernel<<<gcol, 256>>>();
    chargeupd_kernel<<<BN/256, 256>>>(0, cdp, ssp);

    exprow_kernel<1><<<grow, 256>>>();
    colsumP_kernel<<<gcol, 256>>>();
    chargeupd_kernel<<<BN/256, 256>>>(1, cdp, ssp);

    exprow_kernel<2><<<grow, 256>>>();
    colsumP_kernel<<<gcol, 256>>>();
    chargeupd_kernel<<<BN/256, 256>>>(2, cdp, ssp);

    exprow_kernel<3><<<grow, 256>>>();
    colsumP_kernel<<<gcol, 256>>>();
    chargeupd_kernel<<<BN/256, 256>>>(3, cdp, ssp);

    final_fused_kernel<<<BN, 256>>>(out);
}

// round 11
// speedup vs baseline: 1.3564x; 1.3564x over previous
#include <cuda_runtime.h>
#include <cuda_bf16.h>
#include <cstdint>
#include <math.h>

#define NSEQ 4096
#define BATCH 2
#define BN (BATCH*NSEQ)
#define FDIM 512
#define DDIM 64
#define MASKVAL (-12800.0f)
#define SCALE_LOG2E (0.125f*1.4426950408889634f)
#define SQ 72   // padded bf16 row stride for mma smem tiles

// ---------------- scratch (device globals; no allocation allowed) ----------------
__device__ float g_Q[(size_t)BN*DDIM];
__device__ float g_K[(size_t)BN*DDIM];
__device__ float g_C[(size_t)BATCH*NSEQ*NSEQ];   // C' = (QK^T/8)*log2e; above-diag of diag tiles = MASKVAL
__device__ float g_ch[BN];                       // current charge
__device__ float g_chpt[4][BN];                  // transposed packed sqrt(ss)*charge history
__device__ float g_rs[BN];                       // rowsum accumulator
__device__ float g_recv[BN];                     // column sums (received)

__device__ __forceinline__ float sigmoidf_(float x){ return 1.f/(1.f+__expf(-x)); }
__device__ __forceinline__ float ex2_(float x){ float y; asm("ex2.approx.f32 %0, %1;" : "=f"(y) : "f"(x)); return y; }
__device__ __forceinline__ uint32_t smem_u32_(const void* p){
    uint32_t a;
    asm("{ .reg .u64 t; cvta.to.shared.u64 t, %1; cvt.u32.u64 %0, t; }" : "=r"(a) : "l"(p));
    return a;
}

// ---------------- Q/K projection via mma.sync bf16 hi/lo + in-register RoPE ----------------
// block: 64 rows, 256 threads (8 warps). Warps 0-3 -> Q, 4-7 -> K; each warp 16 rows x 64 cols.
// smem layout (bf16 units): Ahi 0, Alo 4608, WQhi 9216, WQlo 13824, WKhi 18432, WKlo 23040
#define QK_SMEM_B (27648*2)

__global__ void __launch_bounds__(256) qk_mma_kernel(const float* __restrict__ feat,
                                                     const float* __restrict__ cosb,
                                                     const float* __restrict__ sinb,
                                                     const float* __restrict__ Wq,
                                                     const float* __restrict__ Wk)
{
    extern __shared__ __nv_bfloat16 sm[];
    __nv_bfloat16* Ahi = sm;
    __nv_bfloat16* Alo = sm + 4608;
    int tid = threadIdx.x, lane = tid & 31, w = tid >> 5;
    long rowbase = (long)blockIdx.x*64;
    int isK = w >> 2;
    int wr0 = (w & 3)*16;
    float acc[8][4] = {};

    for (int f0 = 0; f0 < FDIM; f0 += 64){
        __syncthreads();
        // feat chunk: 64 rows x 64 cols, hi/lo split
        for (int i = tid; i < 64*32; i += 256){
            int r = i >> 5, c2 = i & 31;
            float2 v = *(const float2*)&feat[(rowbase + r)*FDIM + f0 + c2*2];
            __nv_bfloat16 hx = __float2bfloat16_rn(v.x), hy = __float2bfloat16_rn(v.y);
            __nv_bfloat16 lx = __float2bfloat16_rn(v.x - __bfloat162float(hx));
            __nv_bfloat16 ly = __float2bfloat16_rn(v.y - __bfloat162float(hy));
            int o = r*SQ + c2*2;
            *(__nv_bfloat162*)&Ahi[o] = __nv_bfloat162(hx, hy);
            *(__nv_bfloat162*)&Alo[o] = __nv_bfloat162(lx, ly);
        }
        // W chunks [f][d], natural layout (consumed via ldmatrix.trans)
        for (int i = tid; i < 64*32; i += 256){
            int f = i >> 5, c2 = i & 31;
            float2 q = *(const float2*)&Wq[(f0+f)*DDIM + c2*2];
            float2 k = *(const float2*)&Wk[(f0+f)*DDIM + c2*2];
            int o = f*SQ + c2*2;
            __nv_bfloat16 qhx = __float2bfloat16_rn(q.x), qhy = __float2bfloat16_rn(q.y);
            __nv_bfloat16 khx = __float2bfloat16_rn(k.x), khy = __float2bfloat16_rn(k.y);
            __nv_bfloat16 qlx = __float2bfloat16_rn(q.x - __bfloat162float(qhx));
            __nv_bfloat16 qly = __float2bfloat16_rn(q.y - __bfloat162float(qhy));
            __nv_bfloat16 klx = __float2bfloat16_rn(k.x - __bfloat162float(khx));
            __nv_bfloat16 kly = __float2bfloat16_rn(k.y - __bfloat162float(khy));
            *(__nv_bfloat162*)&sm[ 9216 + o] = __nv_bfloat162(qhx, qhy);
            *(__nv_bfloat162*)&sm[13824 + o] = __nv_bfloat162(qlx, qly);
            *(__nv_bfloat162*)&sm[18432 + o] = __nv_bfloat162(khx, khy);
            *(__nv_bfloat162*)&sm[23040 + o] = __nv_bfloat162(klx, kly);
        }
        __syncthreads();

        uint32_t a_hi = smem_u32_(Ahi), a_lo = smem_u32_(Alo);
        uint32_t b_hi = smem_u32_(sm + (isK ? 18432 : 9216));
        uint32_t b_lo = smem_u32_(sm + (isK ? 23040 : 13824));
        #pragma unroll
        for (int combo = 0; combo < 3; combo++){
            uint32_t abase = (combo == 2) ? a_lo : a_hi;
            uint32_t bbase = (combo == 1) ? b_lo : b_hi;
            #pragma unroll
            for (int k0 = 0; k0 < 64; k0 += 16){
                uint32_t a[4];
                uint32_t aaddr = abase + (uint32_t)(((wr0 + (lane & 15))*SQ + k0 + (lane >> 4)*8)*2);
                asm volatile("ldmatrix.sync.aligned.m8n8.x4.shared.b16 {%0,%1,%2,%3}, [%4];"
                    : "=r"(a[0]), "=r"(a[1]), "=r"(a[2]), "=r"(a[3]) : "r"(aaddr));
                #pragma unroll
                for (int j = 0; j < 8; j++){
                    uint32_t b0, b1;
                    uint32_t baddr = bbase + (uint32_t)(((k0 + (lane & 15))*SQ + j*8)*2);
                    asm volatile("ldmatrix.sync.aligned.m8n8.x2.trans.shared.b16 {%0,%1}, [%2];"
                        : "=r"(b0), "=r"(b1) : "r"(baddr));
                    asm volatile("mma.sync.aligned.m16n8k16.row.col.f32.bf16.bf16.f32 "
                        "{%0,%1,%2,%3}, {%4,%5,%6,%7}, {%8,%9}, {%0,%1,%2,%3};"
                        : "+f"(acc[j][0]), "+f"(acc[j][1]), "+f"(acc[j][2]), "+f"(acc[j][3])
                        : "r"(a[0]), "r"(a[1]), "r"(a[2]), "r"(a[3]), "r"(b0), "r"(b1));
                }
            }
        }
    }

    // in-register RoPE + store
    float* outp = isK ? g_K : g_Q;
    int rq = lane >> 2, cq = (lane & 3)*2;
    #pragma unroll
    for (int h = 0; h < 2; h++){
        long n_ = rowbase + wr0 + rq + 8*h;
        int nn = (int)(n_ & (NSEQ-1));
        #pragma unroll
        for (int j = 0; j < 8; j++){
            int d0 = j*8 + cq;
            float v0 = acc[j][2*h], v1 = acc[j][2*h+1];
            float r0, r1;
            if (j < 4){ r0 = -acc[j+4][2*h]; r1 = -acc[j+4][2*h+1]; }
            else      { r0 =  acc[j-4][2*h]; r1 =  acc[j-4][2*h+1]; }
            float2 cs = *(const float2*)&cosb[nn*DDIM + d0];
            float2 sn = *(const float2*)&sinb[nn*DDIM + d0];
            float2 o = make_float2(fmaf(v0, cs.x, r0*sn.x), fmaf(v1, cs.y, r1*sn.y));
            *(float2*)&outp[n_*DDIM + d0] = o;
        }
    }
}

// ---------------- initial charge + zero recv/rs/chpt ----------------
__global__ void charge0_kernel(const float* __restrict__ feat,
                               const float* __restrict__ cw,
                               const float* __restrict__ cb)
{
    int warp = threadIdx.x >> 5, lane = threadIdx.x & 31;
    long n = (long)blockIdx.x*8 + warp;
    if (n >= BN) return;
    float sum = 0.f;
    for (int f = lane; f < FDIM; f += 32) sum = fmaf(feat[n*FDIM+f], cw[f], sum);
    #pragma unroll
    for (int o = 16; o > 0; o >>= 1) sum += __shfl_down_sync(0xffffffffu, sum, o);
    if (lane == 0){
        g_ch[n] = sigmoidf_(sum + cb[0]);
        g_recv[n] = 0.f;
        g_rs[n] = 0.f;
        #pragma unroll
        for (int t = 0; t < 4; t++) g_chpt[t][n] = 0.f;
    }
}

// ---------------- gemm via mma.sync bf16 hi/lo: C' = QK^T*(log2e/8), masked ----------------
__global__ void __launch_bounds__(256) gemm_mma_kernel()
{
    extern __shared__ __nv_bfloat16 smb[];
    __nv_bfloat16* Qhi = smb;
    __nv_bfloat16* Qlo = smb + 128*SQ;
    __nv_bfloat16* Khi = smb + 2*128*SQ;
    __nv_bfloat16* Klo = smb + 3*128*SQ;

    int b = blockIdx.y;
    int kidx = blockIdx.x;
    int ti = (int)((sqrtf(8.f*(float)kidx + 1.f) - 1.f) * 0.5f);
    while ((ti+1)*(ti+2)/2 <= kidx) ti++;
    while (ti*(ti+1)/2 > kidx) ti--;
    int tj = kidx - ti*(ti+1)/2;

    const float* Qb = g_Q + ((long)b*NSEQ + (long)ti*128)*DDIM;
    const float* Kb = g_K + ((long)b*NSEQ + (long)tj*128)*DDIM;
    int tid = threadIdx.x;
    for (int i = tid; i < 128*32; i += 256){
        int r = i >> 5, c2 = i & 31;
        float2 q = *(const float2*)&Qb[r*64 + c2*2];
        float2 k = *(const float2*)&Kb[r*64 + c2*2];
        int o = r*SQ + c2*2;
        __nv_bfloat16 qhx = __float2bfloat16_rn(q.x), qhy = __float2bfloat16_rn(q.y);
        __nv_bfloat16 khx = __float2bfloat16_rn(k.x), khy = __float2bfloat16_rn(k.y);
        __nv_bfloat16 qlx = __float2bfloat16_rn(q.x - __bfloat162float(qhx));
        __nv_bfloat16 qly = __float2bfloat16_rn(q.y - __bfloat162float(qhy));
        __nv_bfloat16 klx = __float2bfloat16_rn(k.x - __bfloat162float(khx));
        __nv_bfloat16 kly = __float2bfloat16_rn(k.y - __bfloat162float(khy));
        *(__nv_bfloat162*)&Qhi[o] = __nv_bfloat162(qhx, qhy);
        *(__nv_bfloat162*)&Qlo[o] = __nv_bfloat162(qlx, qly);
        *(__nv_bfloat162*)&Khi[o] = __nv_bfloat162(khx, khy);
        *(__nv_bfloat162*)&Klo[o] = __nv_bfloat162(klx, kly);
    }
    __syncthreads();

    int lane = tid & 31, w = tid >> 5;
    int wm = (w & 1)*64, wn = (w >> 1)*32;

    float c[4][4][4] = {};

    uint32_t qhi_b = smem_u32_(Qhi), qlo_b = smem_u32_(Qlo);
    uint32_t khi_b = smem_u32_(Khi), klo_b = smem_u32_(Klo);

    int ar = lane & 15, ac8 = lane >> 4;
    int br = lane & 7,  bc8 = (lane >> 3) & 1;

    #pragma unroll
    for (int combo = 0; combo < 3; combo++){
        uint32_t abase = (combo == 2) ? qlo_b : qhi_b;
        uint32_t bbase = (combo == 1) ? klo_b : khi_b;
        #pragma unroll
        for (int k0 = 0; k0 < 64; k0 += 16){
            uint32_t a[4][4], bf[4][2];
            #pragma unroll
            for (int i = 0; i < 4; i++){
                uint32_t addr = abase + (uint32_t)(((wm + i*16 + ar)*SQ + k0 + ac8*8)*2);
                asm volatile("ldmatrix.sync.aligned.m8n8.x4.shared.b16 {%0,%1,%2,%3}, [%4];"
                    : "=r"(a[i][0]), "=r"(a[i][1]), "=r"(a[i][2]), "=r"(a[i][3]) : "r"(addr));
            }
            #pragma unroll
            for (int j = 0; j < 4; j++){
                uint32_t addr = bbase + (uint32_t)(((wn + j*8 + br)*SQ + k0 + bc8*8)*2);
                asm volatile("ldmatrix.sync.aligned.m8n8.x2.shared.b16 {%0,%1}, [%2];"
                    : "=r"(bf[j][0]), "=r"(bf[j][1]) : "r"(addr));
            }
            #pragma unroll
            for (int i = 0; i < 4; i++)
                #pragma unroll
                for (int j = 0; j < 4; j++)
                    asm volatile("mma.sync.aligned.m16n8k16.row.col.f32.bf16.bf16.f32 "
                        "{%0,%1,%2,%3}, {%4,%5,%6,%7}, {%8,%9}, {%0,%1,%2,%3};"
                        : "+f"(c[i][j][0]), "+f"(c[i][j][1]), "+f"(c[i][j][2]), "+f"(c[i][j][3])
                        : "r"(a[i][0]), "r"(a[i][1]), "r"(a[i][2]), "r"(a[i][3]),
                          "r"(bf[j][0]), "r"(bf[j][1]));
        }
    }

    // epilogue: scale, diag mask, direct stores (float2 per frag row)
    float* Cb = g_C + (size_t)b*NSEQ*NSEQ;
    bool diag = (ti == tj);
    int rq = lane >> 2, cq = (lane & 3)*2;
    #pragma unroll
    for (int i = 0; i < 4; i++){
        int lr0 = wm + i*16 + rq;
        #pragma unroll
        for (int j = 0; j < 4; j++){
            int lc = wn + j*8 + cq;
            float2 v0 = make_float2(c[i][j][0]*SCALE_LOG2E, c[i][j][1]*SCALE_LOG2E);
            float2 v1 = make_float2(c[i][j][2]*SCALE_LOG2E, c[i][j][3]*SCALE_LOG2E);
            if (diag){
                if (lr0 < lc)       v0.x = MASKVAL;
                if (lr0 < lc+1)     v0.y = MASKVAL;
                if (lr0+8 < lc)     v1.x = MASKVAL;
                if (lr0+8 < lc+1)   v1.y = MASKVAL;
            }
            size_t row0 = (size_t)(ti*128 + lr0);
            int col = tj*128 + lc;
            *(float2*)&Cb[row0*NSEQ + col] = v0;
            *(float2*)&Cb[(row0+8)*NSEQ + col] = v1;
        }
    }
}

// ---------------- rowsum: warp = 8 rows x 512 cols, T active charge comps ----------------
template<int T>
__global__ void __launch_bounds__(256) rowsum_kernel()
{
    int b  = blockIdx.z;
    int m0 = blockIdx.x * 512;
    int n0 = blockIdx.y * 64;
    if (m0 > n0 + 63) return;
    int lane = threadIdx.x & 31, wid = threadIdx.x >> 5;
    int nr0 = n0 + wid*8;
    const float* Cb = g_C + (size_t)b*NSEQ*NSEQ;
    float acc[8] = {0.f,0.f,0.f,0.f,0.f,0.f,0.f,0.f};
    #pragma unroll
    for (int i = 0; i < 4; i++){
        int mchunk = m0 + i*128;
        if (mchunk > nr0 + 7) break;
        int m = mchunk + lane*4;
        float4 q[(T>0)?T:1];
        #pragma unroll
        for (int t = 0; t < T; t++) q[t] = *(const float4*)&g_chpt[t][b*NSEQ + m];
        #pragma unroll
        for (int r = 0; r < 8; r++){
            int n = nr0 + r;
            float4 cc = __ldg((const float4*)&Cb[(size_t)n*NSEQ + m]);
            float fx = 1.f, fy = 1.f, fz = 1.f, fw = 1.f;
            #pragma unroll
            for (int t = 0; t < T; t++){
                float cn = g_chpt[t][b*NSEQ + n];
                fx = fmaf(cn, q[t].x, fx);
                fy = fmaf(cn, q[t].y, fy);
                fz = fmaf(cn, q[t].z, fz);
                fw = fmaf(cn, q[t].w, fw);
            }
            float e0 = (T==0) ? ex2_(cc.x) : ex2_(cc.x*fx);
            float e1 = (T==0) ? ex2_(cc.y) : ex2_(cc.y*fy);
            float e2 = (T==0) ? ex2_(cc.z) : ex2_(cc.z*fz);
            float e3 = (T==0) ? ex2_(cc.w) : ex2_(cc.w*fw);
            acc[r] += (e0 + e1) + (e2 + e3);
        }
    }
    #pragma unroll
    for (int r = 0; r < 8; r++){
        float s = acc[r];
        #pragma unroll
        for (int o = 16; o > 0; o >>= 1) s += __shfl_down_sync(0xffffffffu, s, o);
        if (lane == 0 && s != 0.f) atomicAdd(&g_rs[b*NSEQ + nr0 + r], s);
    }
}

// ---------------- colsum (received): block = 128 cols x 256 rows ----------------
template<int T>
__global__ void __launch_bounds__(256) colsum_kernel()
{
    int b  = blockIdx.z;
    int m0 = blockIdx.x * 128;
    int n0 = blockIdx.y * 256;
    if (m0 > n0 + 255) return;
    int tid = threadIdx.x, lane = tid & 31, wid = tid >> 5;
    int m = m0 + lane*4;
    float4 q[(T>0)?T:1];
    #pragma unroll
    for (int t = 0; t < T; t++) q[t] = *(const float4*)&g_chpt[t][b*NSEQ + m];
    float4 acc = make_float4(0.f,0.f,0.f,0.f);
    int nbase = n0 + wid*32;
    #pragma unroll 4
    for (int k = 0; k < 32; k++){
        int n = nbase + k;
        if (m0 > n) continue;
        float irs = __frcp_rn(g_rs[b*NSEQ + n]);
        float4 cc = __ldg((const float4*)&g_C[((size_t)b*NSEQ + n)*NSEQ + m]);
        float fx = 1.f, fy = 1.f, fz = 1.f, fw = 1.f;
        #pragma unroll
        for (int t = 0; t < T; t++){
            float cn = g_chpt[t][b*NSEQ + n];
            fx = fmaf(cn, q[t].x, fx);
            fy = fmaf(cn, q[t].y, fy);
            fz = fmaf(cn, q[t].z, fz);
            fw = fmaf(cn, q[t].w, fw);
        }
        acc.x += ((T==0) ? ex2_(cc.x) : ex2_(cc.x*fx))*irs;
        acc.y += ((T==0) ? ex2_(cc.y) : ex2_(cc.y*fy))*irs;
        acc.z += ((T==0) ? ex2_(cc.z) : ex2_(cc.z*fz))*irs;
        acc.w += ((T==0) ? ex2_(cc.w) : ex2_(cc.w*fw))*irs;
    }
    __shared__ float4 s4[256];
    s4[tid] = acc;
    __syncthreads();
    if (tid < 32){
        float4 t = s4[tid];
        #pragma unroll
        for (int r = 1; r < 8; r++){
            float4 o = s4[tid + r*32];
            t.x += o.x; t.y += o.y; t.z += o.z; t.w += o.w;
        }
        float* dst = &g_recv[b*NSEQ + m0 + tid*4];
        atomicAdd(dst+0, t.x);
        atomicAdd(dst+1, t.y);
        atomicAdd(dst+2, t.z);
        atomicAdd(dst+3, t.w);
    }
}

// ---------------- charge update + pack + re-zero recv/rs ----------------
__global__ void chargeupd_kernel(int t, const float* __restrict__ cdp,
                                        const float* __restrict__ ssp)
{
    int i = blockIdx.x*256 + threadIdx.x;
    if (i >= BN) return;
    float cd = *cdp, ss = *ssp;
    float r  = g_recv[i];
    float ch = g_ch[i] * (1.f - cd*sigmoidf_(r - 1.f));
    g_ch[i] = ch;
    g_chpt[t][i] = sqrtf(ss)*ch;
    g_recv[i] = 0.f;
    g_rs[i] = 0.f;
}

// ---------------- fused final: row-strip rowsum + normalized write ----------------
__global__ void __launch_bounds__(256) final_fused_kernel(float* __restrict__ out)
{
    __shared__ float P[NSEQ];
    __shared__ float red[9];
    int blk = blockIdx.x;
    int b = blk & 1;
    int n = (NSEQ-1) - (blk >> 1);           // long rows first
    const float* Crow = g_C + ((size_t)b*NSEQ + n)*NSEQ;
    int tid = threadIdx.x, lane = tid & 31, wid = tid >> 5;
    int L = ((n >> 7) + 1) << 7;             // row length rounded up to 128 (masked tail ~ 0)
    float cn0 = g_chpt[0][b*NSEQ+n];
    float cn1 = g_chpt[1][b*NSEQ+n];
    float cn2 = g_chpt[2][b*NSEQ+n];
    float cn3 = g_chpt[3][b*NSEQ+n];
    float sum = 0.f;
    for (int i = tid; i < (L >> 2); i += 256){
        float4 cc = __ldg(&((const float4*)Crow)[i]);
        int m = b*NSEQ + i*4;
        float4 t0 = *(const float4*)&g_chpt[0][m];
        float4 t1 = *(const float4*)&g_chpt[1][m];
        float4 t2 = *(const float4*)&g_chpt[2][m];
        float4 t3 = *(const float4*)&g_chpt[3][m];
        float fx = fmaf(cn0,t0.x, fmaf(cn1,t1.x, fmaf(cn2,t2.x, fmaf(cn3,t3.x, 1.f))));
        float fy = fmaf(cn0,t0.y, fmaf(cn1,t1.y, fmaf(cn2,t2.y, fmaf(cn3,t3.y, 1.f))));
        float fz = fmaf(cn0,t0.z, fmaf(cn1,t1.z, fmaf(cn2,t2.z, fmaf(cn3,t3.z, 1.f))));
        float fw = fmaf(cn0,t0.w, fmaf(cn1,t1.w, fmaf(cn2,t2.w, fmaf(cn3,t3.w, 1.f))));
        float p0 = ex2_(cc.x*fx), p1 = ex2_(cc.y*fy);
        float p2 = ex2_(cc.z*fz), p3 = ex2_(cc.w*fw);
        *(float4*)&P[i*4] = make_float4(p0,p1,p2,p3);
        sum += (p0 + p1) + (p2 + p3);
    }
    #pragma unroll
    for (int o = 16; o > 0; o >>= 1) sum += __shfl_down_sync(0xffffffffu, sum, o);
    if (lane == 0) red[wid] = sum;
    __syncthreads();
    if (tid == 0){
        float s = 0.f;
        #pragma unroll
        for (int w = 0; w < 8; w++) s += red[w];
        red[8] = 1.f / s;
    }
    __syncthreads();
    float irs = red[8];
    float* orow = out + ((size_t)b*NSEQ + n)*NSEQ;
    int L4 = L >> 2;
    for (int i = tid; i < NSEQ/4; i += 256){
        float4 v = make_float4(0.f,0.f,0.f,0.f);
        if (i < L4){
            float4 p = *(float4*)&P[i*4];
            v = make_float4(p.x*irs, p.y*irs, p.z*irs, p.w*irs);
        }
        __stcs((float4*)&orow[i*4], v);
    }
}

// ---------------- launch ----------------
extern "C" void kernel_launch(void* const* d_in, const int* in_sizes, int n_in,
                              void* d_out, int out_size)
{
    const float* feat = (const float*)d_in[0];
    const float* cosb = (const float*)d_in[1];
    const float* sinb = (const float*)d_in[2];
    // d_in[3] = mask (causal; not needed)
    const float* Wq   = (const float*)d_in[4];
    const float* Wk   = (const float*)d_in[5];
    const float* cw   = (const float*)d_in[6];
    const float* cb   = (const float*)d_in[7];
    const float* ssp  = (const float*)d_in[8];
    const float* cdp  = (const float*)d_in[9];
    float* out = (float*)d_out;

    const int GSMEM = 4*128*SQ*2;   // 73728 bytes
    static int smem_set = 0;
    if (!smem_set){
        cudaFuncSetAttribute(gemm_mma_kernel, cudaFuncAttributeMaxDynamicSharedMemorySize, GSMEM);
        cudaFuncSetAttribute(qk_mma_kernel, cudaFuncAttributeMaxDynamicSharedMemorySize, QK_SMEM_B);
        smem_set = 1;
    }

    qk_mma_kernel<<<BN/64, 256, QK_SMEM_B>>>(feat, cosb, sinb, Wq, Wk);
    charge0_kernel<<<BN/8, 256>>>(feat, cw, cb);

    const int T = NSEQ/128;
    dim3 g3(T*(T+1)/2, BATCH);
    gemm_mma_kernel<<<g3, 256, GSMEM>>>();

    dim3 grow(NSEQ/512, NSEQ/64, BATCH);
    dim3 gcol(NSEQ/128, NSEQ/256, BATCH);

    rowsum_kernel<0><<<grow, 256>>>();
    colsum_kernel<0><<<gcol, 256>>>();
    chargeupd_kernel<<<BN/256, 256>>>(0, cdp, ssp);

    rowsum_kernel<1><<<grow, 256>>>();
    colsum_kernel<1><<<gcol, 256>>>();
    chargeupd_kernel<<<BN/256, 256>>>(1, cdp, ssp);

    rowsum_kernel<2><<<grow, 256>>>();
    colsum_kernel<2><<<gcol, 256>>>();
    chargeupd_kernel<<<BN/256, 256>>>(2, cdp, ssp);

    rowsum_kernel<3><<<grow, 256>>>();
    colsum_kernel<3><<<gcol, 256>>>();
    chargeupd_kernel<<<BN/256, 256>>>(3, cdp, ssp);

    final_fused_kernel<<<BN, 256>>>(out);
}